// round 12
// baseline (speedup 1.0000x reference)
#include <cuda_runtime.h>
#include <cuda_bf16.h>
#include <cuda_fp16.h>
#include <math.h>
#include <stdint.h>

#define L 8192
#define H 128
#define NC 4
#define KS 7
#define LH (L*H)

// ---------------- scratch (static device memory) ----------------
__device__ float g_h [LH];
__device__ float g_Opart[4*LH];                // flash O partials (4 KV splits)
__device__ float g_lp[4*L];                    // flash l partials
__device__ __half g_wf[NC*KS*H*H];             // conv W fp16 [ic][k][o][c]
__device__ __half g_pwf[4*H*H];                // proj W fp16 [mat][o][c] (q,k,v,ff)
__device__ __nv_bfloat16 g_qb[LH];
__device__ __nv_bfloat16 g_kb[LH];
__device__ __half g_vtf[LH];                   // V^T [H][L] fp16

// ================= helpers =================
__device__ __forceinline__ void cp16(uint32_t dst, const void* src) {
    asm volatile("cp.async.cg.shared.global [%0], [%1], 16;\n" :: "r"(dst), "l"(src));
}
__device__ __forceinline__ void ldsm4(uint32_t* r, uint32_t addr) {
    asm volatile("ldmatrix.sync.aligned.m8n8.x4.shared.b16 {%0,%1,%2,%3}, [%4];"
        : "=r"(r[0]), "=r"(r[1]), "=r"(r[2]), "=r"(r[3]) : "r"(addr));
}
// bf16 MMA (flash QK)
__device__ __forceinline__ void mma16816(float* c, const uint32_t* a, uint32_t b0, uint32_t b1) {
    asm volatile("mma.sync.aligned.m16n8k16.row.col.f32.bf16.bf16.f32 "
        "{%0,%1,%2,%3}, {%4,%5,%6,%7}, {%8,%9}, {%0,%1,%2,%3};"
        : "+f"(c[0]), "+f"(c[1]), "+f"(c[2]), "+f"(c[3])
        : "r"(a[0]), "r"(a[1]), "r"(a[2]), "r"(a[3]), "r"(b0), "r"(b1));
}
// fp16 MMA (conv / proj / flash PV)
__device__ __forceinline__ void mma16816h(float* c, const uint32_t* a, uint32_t b0, uint32_t b1) {
    asm volatile("mma.sync.aligned.m16n8k16.row.col.f32.f16.f16.f32 "
        "{%0,%1,%2,%3}, {%4,%5,%6,%7}, {%8,%9}, {%0,%1,%2,%3};"
        : "+f"(c[0]), "+f"(c[1]), "+f"(c[2]), "+f"(c[3])
        : "r"(a[0]), "r"(a[1]), "r"(a[2]), "r"(a[3]), "r"(b0), "r"(b1));
}
__device__ __forceinline__ uint32_t packbf(float a, float b) {
    __nv_bfloat162 p = __floats2bfloat162_rn(a, b);
    return *reinterpret_cast<uint32_t*>(&p);
}
__device__ __forceinline__ uint32_t packh(float a, float b) {
    __half2 p = __floats2half2_rn(a, b);
    return *reinterpret_cast<uint32_t*>(&p);
}
// packed half2 exp2
__device__ __forceinline__ uint32_t ex2h2(uint32_t x) {
    uint32_t r;
    asm("ex2.approx.f16x2 %0, %1;" : "=r"(r) : "r"(x));
    return r;
}

// In-warp LN of one row (lane owns 4 cols), produce fp16 pairs.
__device__ __forceinline__ void ln_row(float4 v, uint32_t& hA, uint32_t& hB) {
    float s = v.x + v.y + v.z + v.w;
    float q = v.x*v.x + v.y*v.y + v.z*v.z + v.w*v.w;
#pragma unroll
    for (int o = 16; o > 0; o >>= 1) {
        s += __shfl_xor_sync(0xffffffffu, s, o);
        q += __shfl_xor_sync(0xffffffffu, q, o);
    }
    float mu  = s * (1.0f / H);
    float var = q * (1.0f / H) - mu * mu;
    float inv = rsqrtf(var + 1e-5f);
    hA = packh((v.x-mu)*inv, (v.y-mu)*inv);
    hB = packh((v.z-mu)*inv, (v.w-mu)*inv);
}

// ---------------- merged prep: conv W fp16 + proj W fp16 + posenc ----------------
__global__ void prep_all_kernel(const float* __restrict__ x,
                                const float* __restrict__ conv_w,
                                const float* __restrict__ Wq, const float* __restrict__ Wk,
                                const float* __restrict__ Wv, const float* __restrict__ Wff,
                                float* __restrict__ h,
                                __half* __restrict__ wf, __half* __restrict__ pwf) {
    int b = blockIdx.x;
    if (b < 1792) {
        int idx = b * 256 + threadIdx.x;       // conv weights: NC*KS*H*H
        int c  = idx & 127;
        int o  = (idx >> 7) & 127;
        int t7 = idx >> 14;
        int k  = t7 % 7;
        int ic = t7 / 7;
        wf[idx] = __float2half_rn(conv_w[(((size_t)ic * H + o) * H + c) * KS + k]);
    } else if (b < 2048) {
        int idx = (b - 1792) * 256 + threadIdx.x;  // 4*16384 proj weights
        int mat = idx >> 14;
        int r = idx & 16383;
        const float* W = (mat == 0) ? Wq : (mat == 1) ? Wk : (mat == 2) ? Wv : Wff;
        pwf[idx] = __float2half_rn(W[r]);
    } else {
        int idx = (b - 2048) * 256 + threadIdx.x;  // posenc: L*H
        int l = idx >> 7, i = idx & 127;
        float di = (float)((i >> 1) << 1);
        float denom = powf(10000.0f, di * (1.0f / 128.0f));
        float ang = (float)l / denom;
        float pe = (i & 1) ? cosf(ang) : sinf(ang);
        h[idx] = x[idx] + pe;
    }
}

// ---------------- conv1d SAME (K=7) via TC fp16 (pure), LN fused, 7 stages ----------------
#define CONV_SMEM (9728 + 65536)
__global__ __launch_bounds__(256) void conv_tc_kernel(
    const float* __restrict__ hin,
    const __half* __restrict__ wf,
    const float* __restrict__ bias, float* __restrict__ h)
{
    extern __shared__ __align__(128) char smem[];
    uint32_t sb = (uint32_t)__cvta_generic_to_shared(smem);
    uint32_t Bbase = sb + 9728;
    int t = threadIdx.x;
    int m0 = blockIdx.x << 5;
    int warp = t >> 5, lane = t & 31;

    auto load_B = [&](int k) {       // full W_k: 32KB
        int buf = k & 1;
#pragma unroll
        for (int i = 0; i < 8; i++) {
            int idx = t + (i << 8);
            int c64 = idx >> 10;
            int o = (idx & 1023) >> 3, ch = idx & 7;
            const __half* src = wf + (size_t)(k * 128 + o) * 128 + c64 * 64 + ch * 8;
            uint32_t dst = Bbase + buf * 32768 + c64 * 16384 + o * 128 + ((ch ^ (o & 7)) << 4);
            cp16(dst, src);
        }
    };

    load_B(0);
    asm volatile("cp.async.commit_group;\n");

    // ---- LN(h) rows m0-3..m0+34 -> A regions (STS) ----
    {
        int c64 = lane >> 4;
        int ch = (lane & 15) >> 1;
        int sub = (lane & 1) << 3;
        for (int r = warp; r < 38; r += 8) {
            int gr = m0 - 3 + r;
            float4 v = make_float4(0.f, 0.f, 0.f, 0.f);
            if (gr >= 0 && gr < L)
                v = *reinterpret_cast<const float4*>(hin + (size_t)gr * H + lane * 4);
            uint32_t hA, hB;
            ln_row(v, hA, hB);
            uint32_t off = r * 128 + ((ch ^ (r & 7)) << 4) + sub;
            *reinterpret_cast<uint2*>(smem + c64 * 4864 + off) = make_uint2(hA, hB);
        }
    }

    int wm = warp >> 2, wn = warp & 3;
    float acc[4][4];
#pragma unroll
    for (int nt = 0; nt < 4; nt++)
#pragma unroll
        for (int i = 0; i < 4; i++) acc[nt][i] = 0.f;

    int rowpat = (lane & 7) + (((lane >> 3) & 1) << 3);
    int chA_hi = (lane >> 4) & 1;
    int rowB = (lane & 7) + ((lane >> 4) << 3);
    int chB_hi = (lane >> 3) & 1;

    for (int s = 0; s < 7; s++) {
        asm volatile("cp.async.wait_group 0;\n");
        __syncthreads();
        if (s + 1 < 7) {
            load_B(s + 1);
            asm volatile("cp.async.commit_group;\n");
        }

        uint32_t Bh = Bbase + (s & 1) * 32768;
        int rA = (wm << 4) + rowpat + s;

#pragma unroll
        for (int c64 = 0; c64 < 2; c64++) {
            uint32_t Areg = sb + c64 * 4864;
            uint32_t Bsub = Bh + c64 * 16384;
#pragma unroll
            for (int k16 = 0; k16 < 4; k16++) {
                int ch = (k16 << 1) + chA_hi;
                uint32_t afr[4];
                ldsm4(afr, Areg + rA * 128 + ((ch ^ (rA & 7)) << 4));

                int chb = (k16 << 1) + chB_hi;
                uint32_t bfr[2][4];
#pragma unroll
                for (int np = 0; np < 2; np++) {
                    int rB = (wn << 5) + (np << 4) + rowB;
                    uint32_t boff = rB * 128 + ((chb ^ (rB & 7)) << 4);
                    ldsm4(bfr[np], Bsub + boff);
                }
#pragma unroll
                for (int nt = 0; nt < 4; nt++) {
                    uint32_t b0 = bfr[nt >> 1][(nt & 1) << 1], b1 = bfr[nt >> 1][((nt & 1) << 1) + 1];
                    mma16816h(acc[nt], afr, b0, b1);
                }
            }
        }
    }

    int g = lane >> 2, tq = lane & 3;
#pragma unroll
    for (int nt = 0; nt < 4; nt++) {
        int r = m0 + (wm << 4) + g;
        int cc = (wn << 5) + (nt << 3) + (tq << 1);
        float b0 = bias[cc], b1 = bias[cc + 1];
        float2 h0 = *reinterpret_cast<float2*>(h + (size_t)r * H + cc);
        float2 h1 = *reinterpret_cast<float2*>(h + (size_t)(r + 8) * H + cc);
        h0.x += acc[nt][0] + b0; h0.y += acc[nt][1] + b1;
        h1.x += acc[nt][2] + b0; h1.y += acc[nt][3] + b1;
        *reinterpret_cast<float2*>(h + (size_t)r * H + cc) = h0;
        *reinterpret_cast<float2*>(h + (size_t)(r + 8) * H + cc) = h1;
    }
}

// ---------------- fp16 TC projection GEMM with fused LN: 64 rows x 128 cols ----------------
// mode 0: QKV (blockIdx.x = mat 0..2): q->bf16*scale, k->bf16, v->V^T fp16
// mode 1: FF with flash-combine folded
#define PROJ_SMEM 81920
__global__ __launch_bounds__(256) void tc_proj_kernel(
    const float* __restrict__ hin,
    const __half* __restrict__ pwf,
    const float* __restrict__ bq, const float* __restrict__ bk, const float* __restrict__ bv,
    __nv_bfloat16* __restrict__ out_q, __nv_bfloat16* __restrict__ out_k,
    __half* __restrict__ out_vt,
    float* __restrict__ out_ff,
    const float* __restrict__ Opart, const float* __restrict__ lp,
    int mode, int matbase, float qscale)
{
    extern __shared__ __align__(128) char smem[];
    uint32_t sb = (uint32_t)__cvta_generic_to_shared(smem);
    float* residS = reinterpret_cast<float*>(smem + 49152);   // [64][128] fp32
    int t = threadIdx.x;
    int mat = blockIdx.x + matbase;
    int m0 = blockIdx.y << 6;
    int warp = t >> 5, lane = t & 31;

    // B: 2 c64 regions of 128 rows x 128B = 16KB, at sb+16384
#pragma unroll
    for (int i = 0; i < 8; i++) {
        int idx = t + (i << 8);
        int c64 = idx >> 10;
        int row = (idx & 1023) >> 3, ch = idx & 7;
        uint32_t dst = sb + 16384 + c64 * 16384 + row * 128 + ((ch ^ (row & 7)) << 4);
        cp16(dst, pwf + (size_t)mat * 16384 + (size_t)row * 128 + c64 * 64 + ch * 8);
    }
    asm volatile("cp.async.commit_group;\n");

    // ---- LN rows m0..m0+63 -> A regions (STS), overlapped with B cp.async ----
    {
        int c64 = lane >> 4;
        int ch = (lane & 15) >> 1;
        int sub = (lane & 1) << 3;
#pragma unroll
        for (int rr = 0; rr < 8; rr++) {
            int r = warp + (rr << 3);
            int gr = m0 + r;
            float4 v = *reinterpret_cast<const float4*>(hin + (size_t)gr * H + lane * 4);
            if (mode == 1) {
                float linv = 1.0f / (lp[gr] + lp[L + gr] + lp[2*L + gr] + lp[3*L + gr]);
                size_t oi = (size_t)gr * H + lane * 4;
                float4 o0 = *reinterpret_cast<const float4*>(Opart + oi);
                float4 o1 = *reinterpret_cast<const float4*>(Opart + LH + oi);
                float4 o2 = *reinterpret_cast<const float4*>(Opart + 2*(size_t)LH + oi);
                float4 o3 = *reinterpret_cast<const float4*>(Opart + 3*(size_t)LH + oi);
                v.x += (o0.x + o1.x + o2.x + o3.x) * linv;
                v.y += (o0.y + o1.y + o2.y + o3.y) * linv;
                v.z += (o0.z + o1.z + o2.z + o3.z) * linv;
                v.w += (o0.w + o1.w + o2.w + o3.w) * linv;
                *reinterpret_cast<float4*>(residS + r * H + lane * 4) = v;
            }
            uint32_t hA, hB;
            ln_row(v, hA, hB);
            uint32_t off = r * 128 + ((ch ^ (r & 7)) << 4) + sub;
            *reinterpret_cast<uint2*>(smem + c64 * 8192 + off) = make_uint2(hA, hB);
        }
    }
    asm volatile("cp.async.wait_group 0;\n");
    __syncthreads();

    int wm = warp >> 2, wn = warp & 3;
    int rowpat = (lane & 7) + (((lane >> 3) & 1) << 3);
    int chA_hi = (lane >> 4) & 1;
    int rowB = (lane & 7) + ((lane >> 4) << 3);
    int chB_hi = (lane >> 3) & 1;

    float acc[2][4][4];
#pragma unroll
    for (int mt = 0; mt < 2; mt++)
#pragma unroll
        for (int nt = 0; nt < 4; nt++)
#pragma unroll
            for (int i = 0; i < 4; i++) acc[mt][nt][i] = 0.f;

#pragma unroll
    for (int k16 = 0; k16 < 8; k16++) {
        int cr = k16 >> 2, kk = k16 & 3;
        int ch = (kk << 1) + chA_hi;
        uint32_t afr[2][4];
#pragma unroll
        for (int mt = 0; mt < 2; mt++) {
            int rA = (wm << 5) + (mt << 4) + rowpat;
            ldsm4(afr[mt], sb + cr * 8192 + rA * 128 + ((ch ^ (rA & 7)) << 4));
        }
        int chb = (kk << 1) + chB_hi;
        uint32_t bfr[2][4];
#pragma unroll
        for (int np = 0; np < 2; np++) {
            int rB = (wn << 5) + (np << 4) + rowB;
            uint32_t boff = rB * 128 + ((chb ^ (rB & 7)) << 4);
            ldsm4(bfr[np], sb + 16384 + cr * 16384 + boff);
        }
#pragma unroll
        for (int mt = 0; mt < 2; mt++)
#pragma unroll
            for (int nt = 0; nt < 4; nt++) {
                uint32_t b0 = bfr[nt >> 1][(nt & 1) << 1], b1 = bfr[nt >> 1][((nt & 1) << 1) + 1];
                mma16816h(acc[mt][nt], afr[mt], b0, b1);
            }
    }

    int g = lane >> 2, tq = lane & 3;
    const float* bias = (mode == 1) ? bq : (mat == 0 ? bq : (mat == 1 ? bk : bv));
#pragma unroll
    for (int mt = 0; mt < 2; mt++) {
#pragma unroll
        for (int nt = 0; nt < 4; nt++) {
            int rl = (wm << 5) + (mt << 4) + g;
            int r = m0 + rl;
            int c = (wn << 5) + (nt << 3) + (tq << 1);
            float b0 = bias[c], b1 = bias[c + 1];
            float v0 = acc[mt][nt][0] + b0, v1 = acc[mt][nt][1] + b1;
            float v2 = acc[mt][nt][2] + b0, v3 = acc[mt][nt][3] + b1;
            size_t ci0 = (size_t)r * H + c, ci1 = (size_t)(r + 8) * H + c;
            if (mode == 1) {
                float2 r0 = *reinterpret_cast<const float2*>(residS + rl * H + c);
                float2 r1 = *reinterpret_cast<const float2*>(residS + (rl + 8) * H + c);
                *reinterpret_cast<float2*>(out_ff + ci0) =
                    make_float2(fmaxf(v0, 0.f) + r0.x, fmaxf(v1, 0.f) + r0.y);
                *reinterpret_cast<float2*>(out_ff + ci1) =
                    make_float2(fmaxf(v2, 0.f) + r1.x, fmaxf(v3, 0.f) + r1.y);
            } else if (mat == 0) {
                *reinterpret_cast<uint32_t*>(out_q + ci0) = packbf(v0 * qscale, v1 * qscale);
                *reinterpret_cast<uint32_t*>(out_q + ci1) = packbf(v2 * qscale, v3 * qscale);
            } else if (mat == 1) {
                *reinterpret_cast<uint32_t*>(out_k + ci0) = packbf(v0, v1);
                *reinterpret_cast<uint32_t*>(out_k + ci1) = packbf(v2, v3);
            } else {
                out_vt[(size_t)c * L + r]           = __float2half_rn(v0);
                out_vt[(size_t)(c + 1) * L + r]     = __float2half_rn(v1);
                out_vt[(size_t)c * L + r + 8]       = __float2half_rn(v2);
                out_vt[(size_t)(c + 1) * L + r + 8] = __float2half_rn(v3);
            }
        }
    }
}

// ---------------- fused flash attention, KV tiles of 64, 2 blocks/SM ----------------
// q pre-scaled by log2(e)/sqrt(H). P = exp2(S) via packed fp16 MUFU; PV in fp16.
#define FA_SMEM (32768 + 65536)
__global__ __launch_bounds__(256, 2) void flash_kernel(
    const __nv_bfloat16* __restrict__ qb,
    const __nv_bfloat16* __restrict__ kb,
    const __half* __restrict__ vt,
    float* __restrict__ Opart, float* __restrict__ lpart)
{
    extern __shared__ __align__(128) char smem[];
    uint32_t sb = (uint32_t)__cvta_generic_to_shared(smem);
    uint32_t Qb = sb;
    uint32_t KVb = sb + 32768;
    int t = threadIdx.x;
    int warp = t >> 5, lane = t & 31;
    int split = blockIdx.x;
    int m0 = blockIdx.y << 7;
    int j0base = split << 11;

#pragma unroll
    for (int i = 0; i < 8; i++) {
        int idx = t + (i << 8);
        int reg = idx >> 10, rem = idx & 1023;
        int row = rem >> 3, ch = rem & 7;
        uint32_t dst = Qb + reg * 16384 + row * 128 + ((ch ^ (row & 7)) << 4);
        cp16(dst, qb + (size_t)(m0 + row) * H + reg * 64 + ch * 8);
    }
    auto loadKV = [&](int it) {
        int b = it & 1;
        int j0 = j0base + (it << 6);
        uint32_t base = KVb + b * 32768;
#pragma unroll
        for (int i = 0; i < 4; i++) {
            int idx = t + (i << 8);
            int reg = idx >> 9, rem = idx & 511;
            int row = rem >> 3, ch = rem & 7;
            cp16(base + reg * 8192 + row * 128 + ((ch ^ (row & 7)) << 4),
                 kb + (size_t)(j0 + row) * H + reg * 64 + ch * 8);
        }
#pragma unroll
        for (int i = 0; i < 4; i++) {
            int idx = t + (i << 8);
            int d = idx >> 3, ch = idx & 7;
            cp16(base + 16384 + d * 128 + ((ch ^ (d & 7)) << 4),
                 vt + (size_t)d * L + j0 + ch * 8);
        }
    };
    loadKV(0);
    asm volatile("cp.async.commit_group;\n");

    float acc_o[16][4];
#pragma unroll
    for (int nt = 0; nt < 16; nt++)
#pragma unroll
        for (int i = 0; i < 4; i++) acc_o[nt][i] = 0.f;
    float lsum0 = 0.f, lsum1 = 0.f;

    int rowpat = (lane & 7) + (((lane >> 3) & 1) << 3);
    int chA_hi = (lane >> 4) & 1;
    int rowB = (lane & 7) + ((lane >> 4) << 3);
    int chB_hi = (lane >> 3) & 1;
    int rA = (warp << 4) + rowpat;

    for (int it = 0; it < 32; it++) {
        asm volatile("cp.async.wait_group 0;\n");
        __syncthreads();
        if (it + 1 < 32) {
            loadKV(it + 1);
            asm volatile("cp.async.commit_group;\n");
        }
        int b = it & 1;
        uint32_t Kbase = KVb + b * 32768;
        uint32_t Vbase = Kbase + 16384;

        uint32_t pP[8][2];
        __half2 A2 = __floats2half2_rn(0.f, 0.f);
        __half2 B2 = __floats2half2_rn(0.f, 0.f);
#pragma unroll
        for (int half = 0; half < 2; half++) {
            float accs[4][4];
#pragma unroll
            for (int nt = 0; nt < 4; nt++)
#pragma unroll
                for (int i = 0; i < 4; i++) accs[nt][i] = 0.f;
#pragma unroll
            for (int cr = 0; cr < 2; cr++) {
#pragma unroll
                for (int k16 = 0; k16 < 4; k16++) {
                    int ch = (k16 << 1) + chA_hi;
                    uint32_t afr[4];
                    ldsm4(afr, Qb + cr * 16384 + rA * 128 + ((ch ^ (rA & 7)) << 4));
                    int chb = (k16 << 1) + chB_hi;
#pragma unroll
                    for (int nd = 0; nd < 2; nd++) {
                        int rB = (half << 5) + (nd << 4) + rowB;
                        uint32_t bfr[4];
                        ldsm4(bfr, Kbase + cr * 8192 + rB * 128 + ((chb ^ (rB & 7)) << 4));
                        mma16816(accs[nd * 2],     afr, bfr[0], bfr[1]);
                        mma16816(accs[nd * 2 + 1], afr, bfr[2], bfr[3]);
                    }
                }
            }
#pragma unroll
            for (int nt = 0; nt < 4; nt++) {
                uint32_t p01 = ex2h2(packh(accs[nt][0], accs[nt][1]));
                uint32_t p23 = ex2h2(packh(accs[nt][2], accs[nt][3]));
                pP[half * 4 + nt][0] = p01;
                pP[half * 4 + nt][1] = p23;
                A2 = __hadd2(A2, *reinterpret_cast<__half2*>(&p01));
                B2 = __hadd2(B2, *reinterpret_cast<__half2*>(&p23));
            }
        }
        float2 fa = __half22float2(A2);
        float2 fb = __half22float2(B2);
        lsum0 += fa.x + fa.y;
        lsum1 += fb.x + fb.y;

#pragma unroll
        for (int kk = 0; kk < 4; kk++) {
            uint32_t a[4] = {pP[kk*2][0], pP[kk*2][1], pP[kk*2+1][0], pP[kk*2+1][1]};
            int chb = (kk << 1) + chB_hi;
#pragma unroll
            for (int nd = 0; nd < 8; nd++) {
                int rB = (nd << 4) + rowB;
                uint32_t bfr[4];
                ldsm4(bfr, Vbase + rB * 128 + ((chb ^ (rB & 7)) << 4));
                mma16816h(acc_o[nd * 2],     a, bfr[0], bfr[1]);
                mma16816h(acc_o[nd * 2 + 1], a, bfr[2], bfr[3]);
            }
        }
    }

    int g = lane >> 2, tq = lane & 3;
    int row0 = m0 + (warp << 4) + g;
    float* Op = Opart + (size_t)split * LH;
#pragma unroll
    for (int nt = 0; nt < 16; nt++) {
        int cc = (nt << 3) + (tq << 1);
        *reinterpret_cast<float2*>(Op + (size_t)row0 * H + cc) = make_float2(acc_o[nt][0], acc_o[nt][1]);
        *reinterpret_cast<float2*>(Op + (size_t)(row0 + 8) * H + cc) = make_float2(acc_o[nt][2], acc_o[nt][3]);
    }
    lsum0 += __shfl_xor_sync(0xffffffffu, lsum0, 1);
    lsum0 += __shfl_xor_sync(0xffffffffu, lsum0, 2);
    lsum1 += __shfl_xor_sync(0xffffffffu, lsum1, 1);
    lsum1 += __shfl_xor_sync(0xffffffffu, lsum1, 2);
    if (tq == 0) {
        lpart[split * L + row0] = lsum0;
        lpart[split * L + row0 + 8] = lsum1;
    }
}

// ---------------- launch ----------------
extern "C" void kernel_launch(void* const* d_in, const int* in_sizes, int n_in,
                              void* d_out, int out_size) {
    const float* x      = (const float*)d_in[0];
    const float* conv_w = (const float*)d_in[1];
    const float* conv_b = (const float*)d_in[2];
    const float* Wq     = (const float*)d_in[3];
    const float* bq     = (const float*)d_in[4];
    const float* Wk     = (const float*)d_in[5];
    const float* bk     = (const float*)d_in[6];
    const float* Wv     = (const float*)d_in[7];
    const float* bv     = (const float*)d_in[8];
    const float* Wff    = (const float*)d_in[9];
    const float* bff    = (const float*)d_in[10];
    float* out = (float*)d_out;

    float *p_h, *p_Op, *p_lp;
    __half *p_wf, *p_pwf, *p_vtf;
    __nv_bfloat16 *p_qb, *p_kb;
    cudaGetSymbolAddress((void**)&p_h,   g_h);
    cudaGetSymbolAddress((void**)&p_Op,  g_Opart);
    cudaGetSymbolAddress((void**)&p_lp,  g_lp);
    cudaGetSymbolAddress((void**)&p_wf,  g_wf);
    cudaGetSymbolAddress((void**)&p_pwf, g_pwf);
    cudaGetSymbolAddress((void**)&p_qb,  g_qb);
    cudaGetSymbolAddress((void**)&p_kb,  g_kb);
    cudaGetSymbolAddress((void**)&p_vtf, g_vtf);

    static int s_attr_done = 0;
    if (!s_attr_done) {
        cudaFuncSetAttribute(conv_tc_kernel, cudaFuncAttributeMaxDynamicSharedMemorySize, CONV_SMEM);
        cudaFuncSetAttribute(flash_kernel, cudaFuncAttributeMaxDynamicSharedMemorySize, FA_SMEM);
        cudaFuncSetAttribute(tc_proj_kernel, cudaFuncAttributeMaxDynamicSharedMemorySize, PROJ_SMEM);
        s_attr_done = 1;
    }

    // q scale folded with log2(e) so flash uses exp2 directly
    const float scale = 0.08838834764831845f * 1.4426950408889634f;

    prep_all_kernel<<<6144, 256>>>(x, conv_w, Wq, Wk, Wv, Wff, p_h, p_wf, p_pwf);

    for (int ic = 0; ic < NC; ic++) {
        conv_tc_kernel<<<256, 256, CONV_SMEM>>>(p_h,
                                                p_wf + (size_t)ic * KS * H * H,
                                                conv_b + ic * H, p_h);
    }

    // attention: QKV proj with fused LN; V written transposed fp16
    tc_proj_kernel<<<dim3(3, 128), 256, PROJ_SMEM>>>(
        p_h, p_pwf, bq, bk, bv,
        p_qb, p_kb, p_vtf, nullptr, nullptr, nullptr, 0, 0, scale);

    flash_kernel<<<dim3(4, 64), 256, FA_SMEM>>>(p_qb, p_kb, p_vtf, p_Op, p_lp);

    // feed-forward with fused LN + flash-combine folded in
    tc_proj_kernel<<<dim3(1, 128), 256, PROJ_SMEM>>>(
        p_h, p_pwf, bff, nullptr, nullptr,
        nullptr, nullptr, nullptr, out, p_Op, p_lp, 1, 3, 1.f);
}

// round 14
// speedup vs baseline: 1.0589x; 1.0589x over previous
#include <cuda_runtime.h>
#include <cuda_bf16.h>
#include <cuda_fp16.h>
#include <math.h>
#include <stdint.h>

#define L 8192
#define H 128
#define NC 4
#define KS 7
#define LH (L*H)

// ---------------- scratch (static device memory) ----------------
__device__ float g_h [LH];
__device__ float g_Opart[2*LH];                // flash O partials (2 KV splits)
__device__ float g_lp[2*L];                    // flash l partials
__device__ __half g_wf[NC*KS*H*H];             // conv W fp16 [ic][k][o][c]
__device__ __half g_pwf[4*H*H];                // proj W fp16 [mat][o][c] (q,k,v,ff)
__device__ __nv_bfloat16 g_qb[LH];
__device__ __nv_bfloat16 g_kb[LH];
__device__ __half g_vtf[LH];                   // V^T [H][L] fp16

// ================= helpers =================
__device__ __forceinline__ void cp16(uint32_t dst, const void* src) {
    asm volatile("cp.async.cg.shared.global [%0], [%1], 16;\n" :: "r"(dst), "l"(src));
}
__device__ __forceinline__ void ldsm4(uint32_t* r, uint32_t addr) {
    asm volatile("ldmatrix.sync.aligned.m8n8.x4.shared.b16 {%0,%1,%2,%3}, [%4];"
        : "=r"(r[0]), "=r"(r[1]), "=r"(r[2]), "=r"(r[3]) : "r"(addr));
}
// bf16 MMA (flash QK)
__device__ __forceinline__ void mma16816(float* c, const uint32_t* a, uint32_t b0, uint32_t b1) {
    asm volatile("mma.sync.aligned.m16n8k16.row.col.f32.bf16.bf16.f32 "
        "{%0,%1,%2,%3}, {%4,%5,%6,%7}, {%8,%9}, {%0,%1,%2,%3};"
        : "+f"(c[0]), "+f"(c[1]), "+f"(c[2]), "+f"(c[3])
        : "r"(a[0]), "r"(a[1]), "r"(a[2]), "r"(a[3]), "r"(b0), "r"(b1));
}
// fp16 MMA (conv / proj / flash PV)
__device__ __forceinline__ void mma16816h(float* c, const uint32_t* a, uint32_t b0, uint32_t b1) {
    asm volatile("mma.sync.aligned.m16n8k16.row.col.f32.f16.f16.f32 "
        "{%0,%1,%2,%3}, {%4,%5,%6,%7}, {%8,%9}, {%0,%1,%2,%3};"
        : "+f"(c[0]), "+f"(c[1]), "+f"(c[2]), "+f"(c[3])
        : "r"(a[0]), "r"(a[1]), "r"(a[2]), "r"(a[3]), "r"(b0), "r"(b1));
}
__device__ __forceinline__ uint32_t packbf(float a, float b) {
    __nv_bfloat162 p = __floats2bfloat162_rn(a, b);
    return *reinterpret_cast<uint32_t*>(&p);
}
__device__ __forceinline__ uint32_t packh(float a, float b) {
    __half2 p = __floats2half2_rn(a, b);
    return *reinterpret_cast<uint32_t*>(&p);
}
__device__ __forceinline__ uint32_t ex2h2(uint32_t x) {
    uint32_t r;
    asm("ex2.approx.f16x2 %0, %1;" : "=r"(r) : "r"(x));
    return r;
}

// In-warp LN of one row (lane owns 4 cols), produce fp16 pairs.
__device__ __forceinline__ void ln_row(float4 v, uint32_t& hA, uint32_t& hB) {
    float s = v.x + v.y + v.z + v.w;
    float q = v.x*v.x + v.y*v.y + v.z*v.z + v.w*v.w;
#pragma unroll
    for (int o = 16; o > 0; o >>= 1) {
        s += __shfl_xor_sync(0xffffffffu, s, o);
        q += __shfl_xor_sync(0xffffffffu, q, o);
    }
    float mu  = s * (1.0f / H);
    float var = q * (1.0f / H) - mu * mu;
    float inv = rsqrtf(var + 1e-5f);
    hA = packh((v.x-mu)*inv, (v.y-mu)*inv);
    hB = packh((v.z-mu)*inv, (v.w-mu)*inv);
}

// ---------------- merged prep ----------------
__global__ void prep_all_kernel(const float* __restrict__ x,
                                const float* __restrict__ conv_w,
                                const float* __restrict__ Wq, const float* __restrict__ Wk,
                                const float* __restrict__ Wv, const float* __restrict__ Wff,
                                float* __restrict__ h,
                                __half* __restrict__ wf, __half* __restrict__ pwf) {
    int b = blockIdx.x;
    if (b < 1792) {
        int idx = b * 256 + threadIdx.x;
        int c  = idx & 127;
        int o  = (idx >> 7) & 127;
        int t7 = idx >> 14;
        int k  = t7 % 7;
        int ic = t7 / 7;
        wf[idx] = __float2half_rn(conv_w[(((size_t)ic * H + o) * H + c) * KS + k]);
    } else if (b < 2048) {
        int idx = (b - 1792) * 256 + threadIdx.x;
        int mat = idx >> 14;
        int r = idx & 16383;
        const float* W = (mat == 0) ? Wq : (mat == 1) ? Wk : (mat == 2) ? Wv : Wff;
        pwf[idx] = __float2half_rn(W[r]);
    } else {
        int idx = (b - 2048) * 256 + threadIdx.x;
        int l = idx >> 7, i = idx & 127;
        float di = (float)((i >> 1) << 1);
        float denom = powf(10000.0f, di * (1.0f / 128.0f));
        float ang = (float)l / denom;
        float pe = (i & 1) ? cosf(ang) : sinf(ang);
        h[idx] = x[idx] + pe;
    }
}

// ---------------- conv1d SAME (K=7) via TC fp16 (pure), LN fused, 7 stages ----------------
#define CONV_SMEM (9728 + 65536)
__global__ __launch_bounds__(256) void conv_tc_kernel(
    const float* __restrict__ hin,
    const __half* __restrict__ wf,
    const float* __restrict__ bias, float* __restrict__ h)
{
    extern __shared__ __align__(128) char smem[];
    uint32_t sb = (uint32_t)__cvta_generic_to_shared(smem);
    uint32_t Bbase = sb + 9728;
    int t = threadIdx.x;
    int m0 = blockIdx.x << 5;
    int warp = t >> 5, lane = t & 31;

    auto load_B = [&](int k) {
        int buf = k & 1;
#pragma unroll
        for (int i = 0; i < 8; i++) {
            int idx = t + (i << 8);
            int c64 = idx >> 10;
            int o = (idx & 1023) >> 3, ch = idx & 7;
            const __half* src = wf + (size_t)(k * 128 + o) * 128 + c64 * 64 + ch * 8;
            uint32_t dst = Bbase + buf * 32768 + c64 * 16384 + o * 128 + ((ch ^ (o & 7)) << 4);
            cp16(dst, src);
        }
    };

    load_B(0);
    asm volatile("cp.async.commit_group;\n");

    {
        int c64 = lane >> 4;
        int ch = (lane & 15) >> 1;
        int sub = (lane & 1) << 3;
        for (int r = warp; r < 38; r += 8) {
            int gr = m0 - 3 + r;
            float4 v = make_float4(0.f, 0.f, 0.f, 0.f);
            if (gr >= 0 && gr < L)
                v = *reinterpret_cast<const float4*>(hin + (size_t)gr * H + lane * 4);
            uint32_t hA, hB;
            ln_row(v, hA, hB);
            uint32_t off = r * 128 + ((ch ^ (r & 7)) << 4) + sub;
            *reinterpret_cast<uint2*>(smem + c64 * 4864 + off) = make_uint2(hA, hB);
        }
    }

    int wm = warp >> 2, wn = warp & 3;
    float acc[4][4];
#pragma unroll
    for (int nt = 0; nt < 4; nt++)
#pragma unroll
        for (int i = 0; i < 4; i++) acc[nt][i] = 0.f;

    int rowpat = (lane & 7) + (((lane >> 3) & 1) << 3);
    int chA_hi = (lane >> 4) & 1;
    int rowB = (lane & 7) + ((lane >> 4) << 3);
    int chB_hi = (lane >> 3) & 1;

    for (int s = 0; s < 7; s++) {
        asm volatile("cp.async.wait_group 0;\n");
        __syncthreads();
        if (s + 1 < 7) {
            load_B(s + 1);
            asm volatile("cp.async.commit_group;\n");
        }

        uint32_t Bh = Bbase + (s & 1) * 32768;
        int rA = (wm << 4) + rowpat + s;

#pragma unroll
        for (int c64 = 0; c64 < 2; c64++) {
            uint32_t Areg = sb + c64 * 4864;
            uint32_t Bsub = Bh + c64 * 16384;
#pragma unroll
            for (int k16 = 0; k16 < 4; k16++) {
                int ch = (k16 << 1) + chA_hi;
                uint32_t afr[4];
                ldsm4(afr, Areg + rA * 128 + ((ch ^ (rA & 7)) << 4));

                int chb = (k16 << 1) + chB_hi;
                uint32_t bfr[2][4];
#pragma unroll
                for (int np = 0; np < 2; np++) {
                    int rB = (wn << 5) + (np << 4) + rowB;
                    uint32_t boff = rB * 128 + ((chb ^ (rB & 7)) << 4);
                    ldsm4(bfr[np], Bsub + boff);
                }
#pragma unroll
                for (int nt = 0; nt < 4; nt++) {
                    uint32_t b0 = bfr[nt >> 1][(nt & 1) << 1], b1 = bfr[nt >> 1][((nt & 1) << 1) + 1];
                    mma16816h(acc[nt], afr, b0, b1);
                }
            }
        }
    }

    int g = lane >> 2, tq = lane & 3;
#pragma unroll
    for (int nt = 0; nt < 4; nt++) {
        int r = m0 + (wm << 4) + g;
        int cc = (wn << 5) + (nt << 3) + (tq << 1);
        float b0 = bias[cc], b1 = bias[cc + 1];
        float2 h0 = *reinterpret_cast<float2*>(h + (size_t)r * H + cc);
        float2 h1 = *reinterpret_cast<float2*>(h + (size_t)(r + 8) * H + cc);
        h0.x += acc[nt][0] + b0; h0.y += acc[nt][1] + b1;
        h1.x += acc[nt][2] + b0; h1.y += acc[nt][3] + b1;
        *reinterpret_cast<float2*>(h + (size_t)r * H + cc) = h0;
        *reinterpret_cast<float2*>(h + (size_t)(r + 8) * H + cc) = h1;
    }
}

// ---------------- fp16 TC projection GEMM with fused LN ----------------
#define PROJ_SMEM 81920
__global__ __launch_bounds__(256) void tc_proj_kernel(
    const float* __restrict__ hin,
    const __half* __restrict__ pwf,
    const float* __restrict__ bq, const float* __restrict__ bk, const float* __restrict__ bv,
    __nv_bfloat16* __restrict__ out_q, __nv_bfloat16* __restrict__ out_k,
    __half* __restrict__ out_vt,
    float* __restrict__ out_ff,
    const float* __restrict__ Opart, const float* __restrict__ lp,
    int mode, int matbase, float qscale)
{
    extern __shared__ __align__(128) char smem[];
    uint32_t sb = (uint32_t)__cvta_generic_to_shared(smem);
    float* residS = reinterpret_cast<float*>(smem + 49152);
    int t = threadIdx.x;
    int mat = blockIdx.x + matbase;
    int m0 = blockIdx.y << 6;
    int warp = t >> 5, lane = t & 31;

#pragma unroll
    for (int i = 0; i < 8; i++) {
        int idx = t + (i << 8);
        int c64 = idx >> 10;
        int row = (idx & 1023) >> 3, ch = idx & 7;
        uint32_t dst = sb + 16384 + c64 * 16384 + row * 128 + ((ch ^ (row & 7)) << 4);
        cp16(dst, pwf + (size_t)mat * 16384 + (size_t)row * 128 + c64 * 64 + ch * 8);
    }
    asm volatile("cp.async.commit_group;\n");

    {
        int c64 = lane >> 4;
        int ch = (lane & 15) >> 1;
        int sub = (lane & 1) << 3;
#pragma unroll
        for (int rr = 0; rr < 8; rr++) {
            int r = warp + (rr << 3);
            int gr = m0 + r;
            float4 v = *reinterpret_cast<const float4*>(hin + (size_t)gr * H + lane * 4);
            if (mode == 1) {
                float linv = 1.0f / (lp[gr] + lp[L + gr]);
                size_t oi = (size_t)gr * H + lane * 4;
                float4 o0 = *reinterpret_cast<const float4*>(Opart + oi);
                float4 o1 = *reinterpret_cast<const float4*>(Opart + LH + oi);
                v.x += (o0.x + o1.x) * linv;
                v.y += (o0.y + o1.y) * linv;
                v.z += (o0.z + o1.z) * linv;
                v.w += (o0.w + o1.w) * linv;
                *reinterpret_cast<float4*>(residS + r * H + lane * 4) = v;
            }
            uint32_t hA, hB;
            ln_row(v, hA, hB);
            uint32_t off = r * 128 + ((ch ^ (r & 7)) << 4) + sub;
            *reinterpret_cast<uint2*>(smem + c64 * 8192 + off) = make_uint2(hA, hB);
        }
    }
    asm volatile("cp.async.wait_group 0;\n");
    __syncthreads();

    int wm = warp >> 2, wn = warp & 3;
    int rowpat = (lane & 7) + (((lane >> 3) & 1) << 3);
    int chA_hi = (lane >> 4) & 1;
    int rowB = (lane & 7) + ((lane >> 4) << 3);
    int chB_hi = (lane >> 3) & 1;

    float acc[2][4][4];
#pragma unroll
    for (int mt = 0; mt < 2; mt++)
#pragma unroll
        for (int nt = 0; nt < 4; nt++)
#pragma unroll
            for (int i = 0; i < 4; i++) acc[mt][nt][i] = 0.f;

#pragma unroll
    for (int k16 = 0; k16 < 8; k16++) {
        int cr = k16 >> 2, kk = k16 & 3;
        int ch = (kk << 1) + chA_hi;
        uint32_t afr[2][4];
#pragma unroll
        for (int mt = 0; mt < 2; mt++) {
            int rA = (wm << 5) + (mt << 4) + rowpat;
            ldsm4(afr[mt], sb + cr * 8192 + rA * 128 + ((ch ^ (rA & 7)) << 4));
        }
        int chb = (kk << 1) + chB_hi;
        uint32_t bfr[2][4];
#pragma unroll
        for (int np = 0; np < 2; np++) {
            int rB = (wn << 5) + (np << 4) + rowB;
            uint32_t boff = rB * 128 + ((chb ^ (rB & 7)) << 4);
            ldsm4(bfr[np], sb + 16384 + cr * 16384 + boff);
        }
#pragma unroll
        for (int mt = 0; mt < 2; mt++)
#pragma unroll
            for (int nt = 0; nt < 4; nt++) {
                uint32_t b0 = bfr[nt >> 1][(nt & 1) << 1], b1 = bfr[nt >> 1][((nt & 1) << 1) + 1];
                mma16816h(acc[mt][nt], afr[mt], b0, b1);
            }
    }

    int g = lane >> 2, tq = lane & 3;
    const float* bias = (mode == 1) ? bq : (mat == 0 ? bq : (mat == 1 ? bk : bv));
#pragma unroll
    for (int mt = 0; mt < 2; mt++) {
#pragma unroll
        for (int nt = 0; nt < 4; nt++) {
            int rl = (wm << 5) + (mt << 4) + g;
            int r = m0 + rl;
            int c = (wn << 5) + (nt << 3) + (tq << 1);
            float b0 = bias[c], b1 = bias[c + 1];
            float v0 = acc[mt][nt][0] + b0, v1 = acc[mt][nt][1] + b1;
            float v2 = acc[mt][nt][2] + b0, v3 = acc[mt][nt][3] + b1;
            size_t ci0 = (size_t)r * H + c, ci1 = (size_t)(r + 8) * H + c;
            if (mode == 1) {
                float2 r0 = *reinterpret_cast<const float2*>(residS + rl * H + c);
                float2 r1 = *reinterpret_cast<const float2*>(residS + (rl + 8) * H + c);
                *reinterpret_cast<float2*>(out_ff + ci0) =
                    make_float2(fmaxf(v0, 0.f) + r0.x, fmaxf(v1, 0.f) + r0.y);
                *reinterpret_cast<float2*>(out_ff + ci1) =
                    make_float2(fmaxf(v2, 0.f) + r1.x, fmaxf(v3, 0.f) + r1.y);
            } else if (mat == 0) {
                *reinterpret_cast<uint32_t*>(out_q + ci0) = packbf(v0 * qscale, v1 * qscale);
                *reinterpret_cast<uint32_t*>(out_q + ci1) = packbf(v2 * qscale, v3 * qscale);
            } else if (mat == 1) {
                *reinterpret_cast<uint32_t*>(out_k + ci0) = packbf(v0, v1);
                *reinterpret_cast<uint32_t*>(out_k + ci1) = packbf(v2, v3);
            } else {
                out_vt[(size_t)c * L + r]           = __float2half_rn(v0);
                out_vt[(size_t)(c + 1) * L + r]     = __float2half_rn(v1);
                out_vt[(size_t)c * L + r + 8]       = __float2half_rn(v2);
                out_vt[(size_t)(c + 1) * L + r + 8] = __float2half_rn(v3);
            }
        }
    }
}

// ---------------- fused flash attention, KV tiles of 128, 2 splits, 1 block/SM ----------------
// q pre-scaled by log2(e)/sqrt(H). P = exp2(S) via packed fp16 MUFU; PV fp16.
// smem: Q 32KB + 2 x (K 32KB + V 32KB) = 160KB
#define FA_SMEM (32768 + 131072)
__global__ __launch_bounds__(256, 1) void flash_kernel(
    const __nv_bfloat16* __restrict__ qb,
    const __nv_bfloat16* __restrict__ kb,
    const __half* __restrict__ vt,
    float* __restrict__ Opart, float* __restrict__ lpart)
{
    extern __shared__ __align__(128) char smem[];
    uint32_t sb = (uint32_t)__cvta_generic_to_shared(smem);
    uint32_t Qb = sb;
    uint32_t KVb = sb + 32768;
    int t = threadIdx.x;
    int warp = t >> 5, lane = t & 31;
    int split = blockIdx.x;
    int m0 = blockIdx.y << 7;
    int j0base = split << 12;          // split * 4096

    // Q: 2 c64 regions of 128 rows x 128B
#pragma unroll
    for (int i = 0; i < 8; i++) {
        int idx = t + (i << 8);
        int reg = idx >> 10, rem = idx & 1023;
        int row = rem >> 3, ch = rem & 7;
        uint32_t dst = Qb + reg * 16384 + row * 128 + ((ch ^ (row & 7)) << 4);
        cp16(dst, qb + (size_t)(m0 + row) * H + reg * 64 + ch * 8);
    }
    auto loadKV = [&](int it) {
        int b = it & 1;
        int j0 = j0base + (it << 7);
        uint32_t base = KVb + b * 65536;
        // K: 128 rows, 2 c64 regions of 16KB
#pragma unroll
        for (int i = 0; i < 8; i++) {
            int idx = t + (i << 8);
            int reg = idx >> 10, rem = idx & 1023;
            int row = rem >> 3, ch = rem & 7;
            cp16(base + reg * 16384 + row * 128 + ((ch ^ (row & 7)) << 4),
                 kb + (size_t)(j0 + row) * H + reg * 64 + ch * 8);
        }
        // V^T fp16: 2 jr regions (64 kv cols each) of 128 d-rows x 128B
#pragma unroll
        for (int i = 0; i < 8; i++) {
            int idx = t + (i << 8);
            int jr = idx >> 10, rem = idx & 1023;
            int d = rem >> 3, ch = rem & 7;
            cp16(base + 32768 + jr * 16384 + d * 128 + ((ch ^ (d & 7)) << 4),
                 vt + (size_t)d * L + j0 + jr * 64 + ch * 8);
        }
    };
    loadKV(0);
    asm volatile("cp.async.commit_group;\n");

    float acc_o[16][4];
#pragma unroll
    for (int nt = 0; nt < 16; nt++)
#pragma unroll
        for (int i = 0; i < 4; i++) acc_o[nt][i] = 0.f;
    float lsum0 = 0.f, lsum1 = 0.f;

    int rowpat = (lane & 7) + (((lane >> 3) & 1) << 3);
    int chA_hi = (lane >> 4) & 1;
    int rowB = (lane & 7) + ((lane >> 4) << 3);
    int chB_hi = (lane >> 3) & 1;
    int rA = (warp << 4) + rowpat;

    for (int it = 0; it < 32; it++) {
        asm volatile("cp.async.wait_group 0;\n");
        __syncthreads();
        if (it + 1 < 32) {
            loadKV(it + 1);
            asm volatile("cp.async.commit_group;\n");
        }
        int b = it & 1;
        uint32_t Kbase = KVb + b * 65536;
        uint32_t Vbase = Kbase + 32768;

        // ---- S = Q @ K^T : 16 rows x 128 cols per warp ----
        float accs[16][4];
#pragma unroll
        for (int nt = 0; nt < 16; nt++)
#pragma unroll
            for (int i = 0; i < 4; i++) accs[nt][i] = 0.f;

#pragma unroll
        for (int cr = 0; cr < 2; cr++) {
#pragma unroll
            for (int k16 = 0; k16 < 4; k16++) {
                int ch = (k16 << 1) + chA_hi;
                uint32_t afr[4];
                ldsm4(afr, Qb + cr * 16384 + rA * 128 + ((ch ^ (rA & 7)) << 4));
                int chb = (k16 << 1) + chB_hi;
#pragma unroll
                for (int nd = 0; nd < 8; nd++) {
                    int rB = (nd << 4) + rowB;
                    uint32_t bfr[4];
                    ldsm4(bfr, Kbase + cr * 16384 + rB * 128 + ((chb ^ (rB & 7)) << 4));
                    mma16816(accs[nd * 2],     afr, bfr[0], bfr[1]);
                    mma16816(accs[nd * 2 + 1], afr, bfr[2], bfr[3]);
                }
            }
        }

        // ---- P = exp2(S) packed fp16, row sums ----
        uint32_t pP[16][2];
        __half2 A2 = __floats2half2_rn(0.f, 0.f);
        __half2 B2 = __floats2half2_rn(0.f, 0.f);
#pragma unroll
        for (int nt = 0; nt < 16; nt++) {
            uint32_t p01 = ex2h2(packh(accs[nt][0], accs[nt][1]));
            uint32_t p23 = ex2h2(packh(accs[nt][2], accs[nt][3]));
            pP[nt][0] = p01;
            pP[nt][1] = p23;
            A2 = __hadd2(A2, *reinterpret_cast<__half2*>(&p01));
            B2 = __hadd2(B2, *reinterpret_cast<__half2*>(&p23));
        }
        float2 fa = __half22float2(A2);
        float2 fb = __half22float2(B2);
        lsum0 += fa.x + fa.y;
        lsum1 += fb.x + fb.y;

        // ---- O += P @ V (fp16) ----
#pragma unroll
        for (int kk = 0; kk < 8; kk++) {
            uint32_t a[4] = {pP[kk*2][0], pP[kk*2][1], pP[kk*2+1][0], pP[kk*2+1][1]};
            int jr = kk >> 2;
            int chb = ((kk & 3) << 1) + chB_hi;
#pragma unroll
            for (int nd = 0; nd < 8; nd++) {
                int rB = (nd << 4) + rowB;
                uint32_t bfr[4];
                ldsm4(bfr, Vbase + jr * 16384 + rB * 128 + ((chb ^ (rB & 7)) << 4));
                mma16816h(acc_o[nd * 2],     a, bfr[0], bfr[1]);
                mma16816h(acc_o[nd * 2 + 1], a, bfr[2], bfr[3]);
            }
        }
    }

    int g = lane >> 2, tq = lane & 3;
    int row0 = m0 + (warp << 4) + g;
    float* Op = Opart + (size_t)split * LH;
#pragma unroll
    for (int nt = 0; nt < 16; nt++) {
        int cc = (nt << 3) + (tq << 1);
        *reinterpret_cast<float2*>(Op + (size_t)row0 * H + cc) = make_float2(acc_o[nt][0], acc_o[nt][1]);
        *reinterpret_cast<float2*>(Op + (size_t)(row0 + 8) * H + cc) = make_float2(acc_o[nt][2], acc_o[nt][3]);
    }
    lsum0 += __shfl_xor_sync(0xffffffffu, lsum0, 1);
    lsum0 += __shfl_xor_sync(0xffffffffu, lsum0, 2);
    lsum1 += __shfl_xor_sync(0xffffffffu, lsum1, 1);
    lsum1 += __shfl_xor_sync(0xffffffffu, lsum1, 2);
    if (tq == 0) {
        lpart[split * L + row0] = lsum0;
        lpart[split * L + row0 + 8] = lsum1;
    }
}

// ---------------- launch ----------------
extern "C" void kernel_launch(void* const* d_in, const int* in_sizes, int n_in,
                              void* d_out, int out_size) {
    const float* x      = (const float*)d_in[0];
    const float* conv_w = (const float*)d_in[1];
    const float* conv_b = (const float*)d_in[2];
    const float* Wq     = (const float*)d_in[3];
    const float* bq     = (const float*)d_in[4];
    const float* Wk     = (const float*)d_in[5];
    const float* bk     = (const float*)d_in[6];
    const float* Wv     = (const float*)d_in[7];
    const float* bv     = (const float*)d_in[8];
    const float* Wff    = (const float*)d_in[9];
    const float* bff    = (const float*)d_in[10];
    float* out = (float*)d_out;

    float *p_h, *p_Op, *p_lp;
    __half *p_wf, *p_pwf, *p_vtf;
    __nv_bfloat16 *p_qb, *p_kb;
    cudaGetSymbolAddress((void**)&p_h,   g_h);
    cudaGetSymbolAddress((void**)&p_Op,  g_Opart);
    cudaGetSymbolAddress((void**)&p_lp,  g_lp);
    cudaGetSymbolAddress((void**)&p_wf,  g_wf);
    cudaGetSymbolAddress((void**)&p_pwf, g_pwf);
    cudaGetSymbolAddress((void**)&p_qb,  g_qb);
    cudaGetSymbolAddress((void**)&p_kb,  g_kb);
    cudaGetSymbolAddress((void**)&p_vtf, g_vtf);

    static int s_attr_done = 0;
    if (!s_attr_done) {
        cudaFuncSetAttribute(conv_tc_kernel, cudaFuncAttributeMaxDynamicSharedMemorySize, CONV_SMEM);
        cudaFuncSetAttribute(flash_kernel, cudaFuncAttributeMaxDynamicSharedMemorySize, FA_SMEM);
        cudaFuncSetAttribute(tc_proj_kernel, cudaFuncAttributeMaxDynamicSharedMemorySize, PROJ_SMEM);
        s_attr_done = 1;
    }

    const float scale = 0.08838834764831845f * 1.4426950408889634f;

    prep_all_kernel<<<6144, 256>>>(x, conv_w, Wq, Wk, Wv, Wff, p_h, p_wf, p_pwf);

    for (int ic = 0; ic < NC; ic++) {
        conv_tc_kernel<<<256, 256, CONV_SMEM>>>(p_h,
                                                p_wf + (size_t)ic * KS * H * H,
                                                conv_b + ic * H, p_h);
    }

    tc_proj_kernel<<<dim3(3, 128), 256, PROJ_SMEM>>>(
        p_h, p_pwf, bq, bk, bv,
        p_qb, p_kb, p_vtf, nullptr, nullptr, nullptr, 0, 0, scale);

    flash_kernel<<<dim3(2, 64), 256, FA_SMEM>>>(p_qb, p_kb, p_vtf, p_Op, p_lp);

    tc_proj_kernel<<<dim3(1, 128), 256, PROJ_SMEM>>>(
        p_h, p_pwf, bff, nullptr, nullptr,
        nullptr, nullptr, nullptr, out, p_Op, p_lp, 1, 3, 1.f);
}

// round 15
// speedup vs baseline: 1.0706x; 1.0111x over previous
#include <cuda_runtime.h>
#include <cuda_bf16.h>
#include <cuda_fp16.h>
#include <math.h>
#include <stdint.h>

#define L 8192
#define H 128
#define NC 4
#define KS 7
#define LH (L*H)

// ---------------- scratch (static device memory) ----------------
__device__ float g_h [LH];
__device__ float g_Opart[2*LH];                // flash O partials (2 KV splits)
__device__ float g_lp[2*L];                    // flash l partials
__device__ __half g_wf[NC*KS*H*H];             // conv W fp16 [ic][k][o][c]
__device__ __half g_pwf[4*H*H];                // proj W fp16 [mat][o][c] (q,k,v,ff)
__device__ __nv_bfloat16 g_qb[LH];
__device__ __nv_bfloat16 g_kb[LH];
__device__ __half g_vtf[LH];                   // V^T [H][L] fp16

// ================= helpers =================
__device__ __forceinline__ void cp16(uint32_t dst, const void* src) {
    asm volatile("cp.async.cg.shared.global [%0], [%1], 16;\n" :: "r"(dst), "l"(src));
}
__device__ __forceinline__ void ldsm4(uint32_t* r, uint32_t addr) {
    asm volatile("ldmatrix.sync.aligned.m8n8.x4.shared.b16 {%0,%1,%2,%3}, [%4];"
        : "=r"(r[0]), "=r"(r[1]), "=r"(r[2]), "=r"(r[3]) : "r"(addr));
}
// bf16 MMA (flash QK)
__device__ __forceinline__ void mma16816(float* c, const uint32_t* a, uint32_t b0, uint32_t b1) {
    asm volatile("mma.sync.aligned.m16n8k16.row.col.f32.bf16.bf16.f32 "
        "{%0,%1,%2,%3}, {%4,%5,%6,%7}, {%8,%9}, {%0,%1,%2,%3};"
        : "+f"(c[0]), "+f"(c[1]), "+f"(c[2]), "+f"(c[3])
        : "r"(a[0]), "r"(a[1]), "r"(a[2]), "r"(a[3]), "r"(b0), "r"(b1));
}
// fp16 MMA (conv / proj / flash PV)
__device__ __forceinline__ void mma16816h(float* c, const uint32_t* a, uint32_t b0, uint32_t b1) {
    asm volatile("mma.sync.aligned.m16n8k16.row.col.f32.f16.f16.f32 "
        "{%0,%1,%2,%3}, {%4,%5,%6,%7}, {%8,%9}, {%0,%1,%2,%3};"
        : "+f"(c[0]), "+f"(c[1]), "+f"(c[2]), "+f"(c[3])
        : "r"(a[0]), "r"(a[1]), "r"(a[2]), "r"(a[3]), "r"(b0), "r"(b1));
}
__device__ __forceinline__ uint32_t packbf(float a, float b) {
    __nv_bfloat162 p = __floats2bfloat162_rn(a, b);
    return *reinterpret_cast<uint32_t*>(&p);
}
__device__ __forceinline__ uint32_t packh(float a, float b) {
    __half2 p = __floats2half2_rn(a, b);
    return *reinterpret_cast<uint32_t*>(&p);
}
__device__ __forceinline__ uint32_t ex2h2(uint32_t x) {
    uint32_t r;
    asm("ex2.approx.f16x2 %0, %1;" : "=r"(r) : "r"(x));
    return r;
}

// In-warp LN of one row (lane owns 4 cols), produce fp16 pairs.
__device__ __forceinline__ void ln_row(float4 v, uint32_t& hA, uint32_t& hB) {
    float s = v.x + v.y + v.z + v.w;
    float q = v.x*v.x + v.y*v.y + v.z*v.z + v.w*v.w;
#pragma unroll
    for (int o = 16; o > 0; o >>= 1) {
        s += __shfl_xor_sync(0xffffffffu, s, o);
        q += __shfl_xor_sync(0xffffffffu, q, o);
    }
    float mu  = s * (1.0f / H);
    float var = q * (1.0f / H) - mu * mu;
    float inv = rsqrtf(var + 1e-5f);
    hA = packh((v.x-mu)*inv, (v.y-mu)*inv);
    hB = packh((v.z-mu)*inv, (v.w-mu)*inv);
}

// ---------------- merged prep ----------------
__global__ void prep_all_kernel(const float* __restrict__ x,
                                const float* __restrict__ conv_w,
                                const float* __restrict__ Wq, const float* __restrict__ Wk,
                                const float* __restrict__ Wv, const float* __restrict__ Wff,
                                float* __restrict__ h,
                                __half* __restrict__ wf, __half* __restrict__ pwf) {
    int b = blockIdx.x;
    if (b < 1792) {
        int idx = b * 256 + threadIdx.x;
        int c  = idx & 127;
        int o  = (idx >> 7) & 127;
        int t7 = idx >> 14;
        int k  = t7 % 7;
        int ic = t7 / 7;
        wf[idx] = __float2half_rn(conv_w[(((size_t)ic * H + o) * H + c) * KS + k]);
    } else if (b < 2048) {
        int idx = (b - 1792) * 256 + threadIdx.x;
        int mat = idx >> 14;
        int r = idx & 16383;
        const float* W = (mat == 0) ? Wq : (mat == 1) ? Wk : (mat == 2) ? Wv : Wff;
        pwf[idx] = __float2half_rn(W[r]);
    } else {
        int idx = (b - 2048) * 256 + threadIdx.x;
        int l = idx >> 7, i = idx & 127;
        float di = (float)((i >> 1) << 1);
        float denom = powf(10000.0f, di * (1.0f / 128.0f));
        float ang = (float)l / denom;
        float pe = (i & 1) ? cosf(ang) : sinf(ang);
        h[idx] = x[idx] + pe;
    }
}

// ---------------- conv1d SAME (K=7) via TC fp16 (pure), LN fused, 7 stages ----------------
#define CONV_SMEM (9728 + 65536)
__global__ __launch_bounds__(256) void conv_tc_kernel(
    const float* __restrict__ hin,
    const __half* __restrict__ wf,
    const float* __restrict__ bias, float* __restrict__ h)
{
    extern __shared__ __align__(128) char smem[];
    uint32_t sb = (uint32_t)__cvta_generic_to_shared(smem);
    uint32_t Bbase = sb + 9728;
    int t = threadIdx.x;
    int m0 = blockIdx.x << 5;
    int warp = t >> 5, lane = t & 31;

    auto load_B = [&](int k) {
        int buf = k & 1;
#pragma unroll
        for (int i = 0; i < 8; i++) {
            int idx = t + (i << 8);
            int c64 = idx >> 10;
            int o = (idx & 1023) >> 3, ch = idx & 7;
            const __half* src = wf + (size_t)(k * 128 + o) * 128 + c64 * 64 + ch * 8;
            uint32_t dst = Bbase + buf * 32768 + c64 * 16384 + o * 128 + ((ch ^ (o & 7)) << 4);
            cp16(dst, src);
        }
    };

    load_B(0);
    asm volatile("cp.async.commit_group;\n");

    {
        int c64 = lane >> 4;
        int ch = (lane & 15) >> 1;
        int sub = (lane & 1) << 3;
        for (int r = warp; r < 38; r += 8) {
            int gr = m0 - 3 + r;
            float4 v = make_float4(0.f, 0.f, 0.f, 0.f);
            if (gr >= 0 && gr < L)
                v = *reinterpret_cast<const float4*>(hin + (size_t)gr * H + lane * 4);
            uint32_t hA, hB;
            ln_row(v, hA, hB);
            uint32_t off = r * 128 + ((ch ^ (r & 7)) << 4) + sub;
            *reinterpret_cast<uint2*>(smem + c64 * 4864 + off) = make_uint2(hA, hB);
        }
    }

    int wm = warp >> 2, wn = warp & 3;
    float acc[4][4];
#pragma unroll
    for (int nt = 0; nt < 4; nt++)
#pragma unroll
        for (int i = 0; i < 4; i++) acc[nt][i] = 0.f;

    int rowpat = (lane & 7) + (((lane >> 3) & 1) << 3);
    int chA_hi = (lane >> 4) & 1;
    int rowB = (lane & 7) + ((lane >> 4) << 3);
    int chB_hi = (lane >> 3) & 1;

    for (int s = 0; s < 7; s++) {
        asm volatile("cp.async.wait_group 0;\n");
        __syncthreads();
        if (s + 1 < 7) {
            load_B(s + 1);
            asm volatile("cp.async.commit_group;\n");
        }

        uint32_t Bh = Bbase + (s & 1) * 32768;
        int rA = (wm << 4) + rowpat + s;

#pragma unroll
        for (int c64 = 0; c64 < 2; c64++) {
            uint32_t Areg = sb + c64 * 4864;
            uint32_t Bsub = Bh + c64 * 16384;
#pragma unroll
            for (int k16 = 0; k16 < 4; k16++) {
                int ch = (k16 << 1) + chA_hi;
                uint32_t afr[4];
                ldsm4(afr, Areg + rA * 128 + ((ch ^ (rA & 7)) << 4));

                int chb = (k16 << 1) + chB_hi;
                uint32_t bfr[2][4];
#pragma unroll
                for (int np = 0; np < 2; np++) {
                    int rB = (wn << 5) + (np << 4) + rowB;
                    uint32_t boff = rB * 128 + ((chb ^ (rB & 7)) << 4);
                    ldsm4(bfr[np], Bsub + boff);
                }
#pragma unroll
                for (int nt = 0; nt < 4; nt++) {
                    uint32_t b0 = bfr[nt >> 1][(nt & 1) << 1], b1 = bfr[nt >> 1][((nt & 1) << 1) + 1];
                    mma16816h(acc[nt], afr, b0, b1);
                }
            }
        }
    }

    int g = lane >> 2, tq = lane & 3;
#pragma unroll
    for (int nt = 0; nt < 4; nt++) {
        int r = m0 + (wm << 4) + g;
        int cc = (wn << 5) + (nt << 3) + (tq << 1);
        float b0 = bias[cc], b1 = bias[cc + 1];
        float2 h0 = *reinterpret_cast<float2*>(h + (size_t)r * H + cc);
        float2 h1 = *reinterpret_cast<float2*>(h + (size_t)(r + 8) * H + cc);
        h0.x += acc[nt][0] + b0; h0.y += acc[nt][1] + b1;
        h1.x += acc[nt][2] + b0; h1.y += acc[nt][3] + b1;
        *reinterpret_cast<float2*>(h + (size_t)r * H + cc) = h0;
        *reinterpret_cast<float2*>(h + (size_t)(r + 8) * H + cc) = h1;
    }
}

// ---------------- fp16 TC projection GEMM with fused LN ----------------
#define PROJ_SMEM 81920
__global__ __launch_bounds__(256) void tc_proj_kernel(
    const float* __restrict__ hin,
    const __half* __restrict__ pwf,
    const float* __restrict__ bq, const float* __restrict__ bk, const float* __restrict__ bv,
    __nv_bfloat16* __restrict__ out_q, __nv_bfloat16* __restrict__ out_k,
    __half* __restrict__ out_vt,
    float* __restrict__ out_ff,
    const float* __restrict__ Opart, const float* __restrict__ lp,
    int mode, int matbase, float qscale)
{
    extern __shared__ __align__(128) char smem[];
    uint32_t sb = (uint32_t)__cvta_generic_to_shared(smem);
    float* residS = reinterpret_cast<float*>(smem + 49152);
    int t = threadIdx.x;
    int mat = blockIdx.x + matbase;
    int m0 = blockIdx.y << 6;
    int warp = t >> 5, lane = t & 31;

#pragma unroll
    for (int i = 0; i < 8; i++) {
        int idx = t + (i << 8);
        int c64 = idx >> 10;
        int row = (idx & 1023) >> 3, ch = idx & 7;
        uint32_t dst = sb + 16384 + c64 * 16384 + row * 128 + ((ch ^ (row & 7)) << 4);
        cp16(dst, pwf + (size_t)mat * 16384 + (size_t)row * 128 + c64 * 64 + ch * 8);
    }
    asm volatile("cp.async.commit_group;\n");

    {
        int c64 = lane >> 4;
        int ch = (lane & 15) >> 1;
        int sub = (lane & 1) << 3;
#pragma unroll
        for (int rr = 0; rr < 8; rr++) {
            int r = warp + (rr << 3);
            int gr = m0 + r;
            float4 v = *reinterpret_cast<const float4*>(hin + (size_t)gr * H + lane * 4);
            if (mode == 1) {
                float linv = 1.0f / (lp[gr] + lp[L + gr]);
                size_t oi = (size_t)gr * H + lane * 4;
                float4 o0 = *reinterpret_cast<const float4*>(Opart + oi);
                float4 o1 = *reinterpret_cast<const float4*>(Opart + LH + oi);
                v.x += (o0.x + o1.x) * linv;
                v.y += (o0.y + o1.y) * linv;
                v.z += (o0.z + o1.z) * linv;
                v.w += (o0.w + o1.w) * linv;
                *reinterpret_cast<float4*>(residS + r * H + lane * 4) = v;
            }
            uint32_t hA, hB;
            ln_row(v, hA, hB);
            uint32_t off = r * 128 + ((ch ^ (r & 7)) << 4) + sub;
            *reinterpret_cast<uint2*>(smem + c64 * 8192 + off) = make_uint2(hA, hB);
        }
    }
    asm volatile("cp.async.wait_group 0;\n");
    __syncthreads();

    int wm = warp >> 2, wn = warp & 3;
    int rowpat = (lane & 7) + (((lane >> 3) & 1) << 3);
    int chA_hi = (lane >> 4) & 1;
    int rowB = (lane & 7) + ((lane >> 4) << 3);
    int chB_hi = (lane >> 3) & 1;

    float acc[2][4][4];
#pragma unroll
    for (int mt = 0; mt < 2; mt++)
#pragma unroll
        for (int nt = 0; nt < 4; nt++)
#pragma unroll
            for (int i = 0; i < 4; i++) acc[mt][nt][i] = 0.f;

#pragma unroll
    for (int k16 = 0; k16 < 8; k16++) {
        int cr = k16 >> 2, kk = k16 & 3;
        int ch = (kk << 1) + chA_hi;
        uint32_t afr[2][4];
#pragma unroll
        for (int mt = 0; mt < 2; mt++) {
            int rA = (wm << 5) + (mt << 4) + rowpat;
            ldsm4(afr[mt], sb + cr * 8192 + rA * 128 + ((ch ^ (rA & 7)) << 4));
        }
        int chb = (kk << 1) + chB_hi;
        uint32_t bfr[2][4];
#pragma unroll
        for (int np = 0; np < 2; np++) {
            int rB = (wn << 5) + (np << 4) + rowB;
            uint32_t boff = rB * 128 + ((chb ^ (rB & 7)) << 4);
            ldsm4(bfr[np], sb + 16384 + cr * 16384 + boff);
        }
#pragma unroll
        for (int mt = 0; mt < 2; mt++)
#pragma unroll
            for (int nt = 0; nt < 4; nt++) {
                uint32_t b0 = bfr[nt >> 1][(nt & 1) << 1], b1 = bfr[nt >> 1][((nt & 1) << 1) + 1];
                mma16816h(acc[mt][nt], afr[mt], b0, b1);
            }
    }

    int g = lane >> 2, tq = lane & 3;
    const float* bias = (mode == 1) ? bq : (mat == 0 ? bq : (mat == 1 ? bk : bv));
#pragma unroll
    for (int mt = 0; mt < 2; mt++) {
#pragma unroll
        for (int nt = 0; nt < 4; nt++) {
            int rl = (wm << 5) + (mt << 4) + g;
            int r = m0 + rl;
            int c = (wn << 5) + (nt << 3) + (tq << 1);
            float b0 = bias[c], b1 = bias[c + 1];
            float v0 = acc[mt][nt][0] + b0, v1 = acc[mt][nt][1] + b1;
            float v2 = acc[mt][nt][2] + b0, v3 = acc[mt][nt][3] + b1;
            size_t ci0 = (size_t)r * H + c, ci1 = (size_t)(r + 8) * H + c;
            if (mode == 1) {
                float2 r0 = *reinterpret_cast<const float2*>(residS + rl * H + c);
                float2 r1 = *reinterpret_cast<const float2*>(residS + (rl + 8) * H + c);
                *reinterpret_cast<float2*>(out_ff + ci0) =
                    make_float2(fmaxf(v0, 0.f) + r0.x, fmaxf(v1, 0.f) + r0.y);
                *reinterpret_cast<float2*>(out_ff + ci1) =
                    make_float2(fmaxf(v2, 0.f) + r1.x, fmaxf(v3, 0.f) + r1.y);
            } else if (mat == 0) {
                *reinterpret_cast<uint32_t*>(out_q + ci0) = packbf(v0 * qscale, v1 * qscale);
                *reinterpret_cast<uint32_t*>(out_q + ci1) = packbf(v2 * qscale, v3 * qscale);
            } else if (mat == 1) {
                *reinterpret_cast<uint32_t*>(out_k + ci0) = packbf(v0, v1);
                *reinterpret_cast<uint32_t*>(out_k + ci1) = packbf(v2, v3);
            } else {
                out_vt[(size_t)c * L + r]           = __float2half_rn(v0);
                out_vt[(size_t)(c + 1) * L + r]     = __float2half_rn(v1);
                out_vt[(size_t)c * L + r + 8]       = __float2half_rn(v2);
                out_vt[(size_t)(c + 1) * L + r + 8] = __float2half_rn(v3);
            }
        }
    }
}

// ---------------- fused flash attention, KV-128 tiles, 2 splits, 3-stage ring, Q in regs ----------------
// q pre-scaled by log2(e)/sqrt(H). P = exp2(S) via packed fp16 MUFU; PV fp16.
// smem: Q 32KB + 3 x (K 32KB + V 32KB) = 224KB
#define FA_SMEM (32768 + 3*65536)
__global__ __launch_bounds__(256, 1) void flash_kernel(
    const __nv_bfloat16* __restrict__ qb,
    const __nv_bfloat16* __restrict__ kb,
    const __half* __restrict__ vt,
    float* __restrict__ Opart, float* __restrict__ lpart)
{
    extern __shared__ __align__(128) char smem[];
    uint32_t sb = (uint32_t)__cvta_generic_to_shared(smem);
    uint32_t Qb = sb;
    uint32_t KVb = sb + 32768;
    int t = threadIdx.x;
    int warp = t >> 5, lane = t & 31;
    int split = blockIdx.x;
    int m0 = blockIdx.y << 7;
    int j0base = split << 12;          // split * 4096

    // Q: 2 c64 regions of 128 rows x 128B  (own cp.async group)
#pragma unroll
    for (int i = 0; i < 8; i++) {
        int idx = t + (i << 8);
        int reg = idx >> 10, rem = idx & 1023;
        int row = rem >> 3, ch = rem & 7;
        uint32_t dst = Qb + reg * 16384 + row * 128 + ((ch ^ (row & 7)) << 4);
        cp16(dst, qb + (size_t)(m0 + row) * H + reg * 64 + ch * 8);
    }
    asm volatile("cp.async.commit_group;\n");

    auto loadKV = [&](int it) {
        int b = it % 3;
        int j0 = j0base + (it << 7);
        uint32_t base = KVb + b * 65536;
#pragma unroll
        for (int i = 0; i < 8; i++) {
            int idx = t + (i << 8);
            int reg = idx >> 10, rem = idx & 1023;
            int row = rem >> 3, ch = rem & 7;
            cp16(base + reg * 16384 + row * 128 + ((ch ^ (row & 7)) << 4),
                 kb + (size_t)(j0 + row) * H + reg * 64 + ch * 8);
        }
#pragma unroll
        for (int i = 0; i < 8; i++) {
            int idx = t + (i << 8);
            int jr = idx >> 10, rem = idx & 1023;
            int d = rem >> 3, ch = rem & 7;
            cp16(base + 32768 + jr * 16384 + d * 128 + ((ch ^ (d & 7)) << 4),
                 vt + (size_t)d * L + j0 + jr * 64 + ch * 8);
        }
    };
    loadKV(0);
    asm volatile("cp.async.commit_group;\n");
    loadKV(1);
    asm volatile("cp.async.commit_group;\n");

    int rowpat = (lane & 7) + (((lane >> 3) & 1) << 3);
    int chA_hi = (lane >> 4) & 1;
    int rowB = (lane & 7) + ((lane >> 4) << 3);
    int chB_hi = (lane >> 3) & 1;
    int rA = (warp << 4) + rowpat;

    // Wait for Q (2 KV groups may still be pending), then hoist Q frags to registers.
    asm volatile("cp.async.wait_group 2;\n");
    __syncthreads();
    uint32_t qfr[8][4];     // [cr*4 + k16][4]
#pragma unroll
    for (int cr = 0; cr < 2; cr++)
#pragma unroll
        for (int k16 = 0; k16 < 4; k16++) {
            int ch = (k16 << 1) + chA_hi;
            ldsm4(qfr[cr * 4 + k16], Qb + cr * 16384 + rA * 128 + ((ch ^ (rA & 7)) << 4));
        }

    float acc_o[16][4];
#pragma unroll
    for (int nt = 0; nt < 16; nt++)
#pragma unroll
        for (int i = 0; i < 4; i++) acc_o[nt][i] = 0.f;
    float lsum0 = 0.f, lsum1 = 0.f;

    for (int it = 0; it < 32; it++) {
        if (it + 2 < 32) {
            asm volatile("cp.async.wait_group 1;\n");   // KV(it) done, KV(it+1) may fly
        } else {
            asm volatile("cp.async.wait_group 0;\n");
        }
        __syncthreads();                                // all warps done with compute(it-1)
        if (it + 2 < 32) {
            loadKV(it + 2);                             // overwrites buffer of (it-1): safe
            asm volatile("cp.async.commit_group;\n");
        }
        int b = it % 3;
        uint32_t Kbase = KVb + b * 65536;
        uint32_t Vbase = Kbase + 32768;

        // ---- S = Q @ K^T : 16 rows x 128 cols per warp ----
        float accs[16][4];
#pragma unroll
        for (int nt = 0; nt < 16; nt++)
#pragma unroll
            for (int i = 0; i < 4; i++) accs[nt][i] = 0.f;

#pragma unroll
        for (int cr = 0; cr < 2; cr++) {
#pragma unroll
            for (int k16 = 0; k16 < 4; k16++) {
                const uint32_t* afr = qfr[cr * 4 + k16];
                int chb = (k16 << 1) + chB_hi;
#pragma unroll
                for (int nd = 0; nd < 8; nd++) {
                    int rB = (nd << 4) + rowB;
                    uint32_t bfr[4];
                    ldsm4(bfr, Kbase + cr * 16384 + rB * 128 + ((chb ^ (rB & 7)) << 4));
                    mma16816(accs[nd * 2],     afr, bfr[0], bfr[1]);
                    mma16816(accs[nd * 2 + 1], afr, bfr[2], bfr[3]);
                }
            }
        }

        // ---- P = exp2(S) packed fp16, row sums ----
        uint32_t pP[16][2];
        __half2 A2 = __floats2half2_rn(0.f, 0.f);
        __half2 B2 = __floats2half2_rn(0.f, 0.f);
#pragma unroll
        for (int nt = 0; nt < 16; nt++) {
            uint32_t p01 = ex2h2(packh(accs[nt][0], accs[nt][1]));
            uint32_t p23 = ex2h2(packh(accs[nt][2], accs[nt][3]));
            pP[nt][0] = p01;
            pP[nt][1] = p23;
            A2 = __hadd2(A2, *reinterpret_cast<__half2*>(&p01));
            B2 = __hadd2(B2, *reinterpret_cast<__half2*>(&p23));
        }
        float2 fa = __half22float2(A2);
        float2 fb = __half22float2(B2);
        lsum0 += fa.x + fa.y;
        lsum1 += fb.x + fb.y;

        // ---- O += P @ V (fp16) ----
#pragma unroll
        for (int kk = 0; kk < 8; kk++) {
            uint32_t a[4] = {pP[kk*2][0], pP[kk*2][1], pP[kk*2+1][0], pP[kk*2+1][1]};
            int jr = kk >> 2;
            int chb = ((kk & 3) << 1) + chB_hi;
#pragma unroll
            for (int nd = 0; nd < 8; nd++) {
                int rB = (nd << 4) + rowB;
                uint32_t bfr[4];
                ldsm4(bfr, Vbase + jr * 16384 + rB * 128 + ((chb ^ (rB & 7)) << 4));
                mma16816h(acc_o[nd * 2],     a, bfr[0], bfr[1]);
                mma16816h(acc_o[nd * 2 + 1], a, bfr[2], bfr[3]);
            }
        }
    }

    int g = lane >> 2, tq = lane & 3;
    int row0 = m0 + (warp << 4) + g;
    float* Op = Opart + (size_t)split * LH;
#pragma unroll
    for (int nt = 0; nt < 16; nt++) {
        int cc = (nt << 3) + (tq << 1);
        *reinterpret_cast<float2*>(Op + (size_t)row0 * H + cc) = make_float2(acc_o[nt][0], acc_o[nt][1]);
        *reinterpret_cast<float2*>(Op + (size_t)(row0 + 8) * H + cc) = make_float2(acc_o[nt][2], acc_o[nt][3]);
    }
    lsum0 += __shfl_xor_sync(0xffffffffu, lsum0, 1);
    lsum0 += __shfl_xor_sync(0xffffffffu, lsum0, 2);
    lsum1 += __shfl_xor_sync(0xffffffffu, lsum1, 1);
    lsum1 += __shfl_xor_sync(0xffffffffu, lsum1, 2);
    if (tq == 0) {
        lpart[split * L + row0] = lsum0;
        lpart[split * L + row0 + 8] = lsum1;
    }
}

// ---------------- launch ----------------
extern "C" void kernel_launch(void* const* d_in, const int* in_sizes, int n_in,
                              void* d_out, int out_size) {
    const float* x      = (const float*)d_in[0];
    const float* conv_w = (const float*)d_in[1];
    const float* conv_b = (const float*)d_in[2];
    const float* Wq     = (const float*)d_in[3];
    const float* bq     = (const float*)d_in[4];
    const float* Wk     = (const float*)d_in[5];
    const float* bk     = (const float*)d_in[6];
    const float* Wv     = (const float*)d_in[7];
    const float* bv     = (const float*)d_in[8];
    const float* Wff    = (const float*)d_in[9];
    const float* bff    = (const float*)d_in[10];
    float* out = (float*)d_out;

    float *p_h, *p_Op, *p_lp;
    __half *p_wf, *p_pwf, *p_vtf;
    __nv_bfloat16 *p_qb, *p_kb;
    cudaGetSymbolAddress((void**)&p_h,   g_h);
    cudaGetSymbolAddress((void**)&p_Op,  g_Opart);
    cudaGetSymbolAddress((void**)&p_lp,  g_lp);
    cudaGetSymbolAddress((void**)&p_wf,  g_wf);
    cudaGetSymbolAddress((void**)&p_pwf, g_pwf);
    cudaGetSymbolAddress((void**)&p_qb,  g_qb);
    cudaGetSymbolAddress((void**)&p_kb,  g_kb);
    cudaGetSymbolAddress((void**)&p_vtf, g_vtf);

    static int s_attr_done = 0;
    if (!s_attr_done) {
        cudaFuncSetAttribute(conv_tc_kernel, cudaFuncAttributeMaxDynamicSharedMemorySize, CONV_SMEM);
        cudaFuncSetAttribute(flash_kernel, cudaFuncAttributeMaxDynamicSharedMemorySize, FA_SMEM);
        cudaFuncSetAttribute(tc_proj_kernel, cudaFuncAttributeMaxDynamicSharedMemorySize, PROJ_SMEM);
        s_attr_done = 1;
    }

    const float scale = 0.08838834764831845f * 1.4426950408889634f;

    prep_all_kernel<<<6144, 256>>>(x, conv_w, Wq, Wk, Wv, Wff, p_h, p_wf, p_pwf);

    for (int ic = 0; ic < NC; ic++) {
        conv_tc_kernel<<<256, 256, CONV_SMEM>>>(p_h,
                                                p_wf + (size_t)ic * KS * H * H,
                                                conv_b + ic * H, p_h);
    }

    tc_proj_kernel<<<dim3(3, 128), 256, PROJ_SMEM>>>(
        p_h, p_pwf, bq, bk, bv,
        p_qb, p_kb, p_vtf, nullptr, nullptr, nullptr, 0, 0, scale);

    flash_kernel<<<dim3(2, 64), 256, FA_SMEM>>>(p_qb, p_kb, p_vtf, p_Op, p_lp);

    tc_proj_kernel<<<dim3(1, 128), 256, PROJ_SMEM>>>(
        p_h, p_pwf, bff, nullptr, nullptr,
        nullptr, nullptr, nullptr, out, p_Op, p_lp, 1, 3, 1.f);
}